// round 1
// baseline (speedup 1.0000x reference)
#include <cuda_runtime.h>
#include <cuda_bf16.h>
#include <math.h>

#define D_MODEL 1024
#define N_HEADS 16
#define DK 64
#define B_SZ 2
#define S_LEN 2048
#define M_ROWS (B_SZ * S_LEN)   // 4096

// -------------------- scratch (allocation-free) --------------------
__device__ float g_Q[M_ROWS * D_MODEL];
__device__ float g_K[M_ROWS * D_MODEL];
__device__ float g_V[M_ROWS * D_MODEL];
__device__ float g_AO[M_ROWS * D_MODEL];

// -------------------- SGEMM: Y[M,N] = X[M,K] @ W[N,K]^T + b[N] --------------------
// M=4096, N=1024, K=1024. Block tile 64x64, K-tile 16, 256 threads, 4x4 per thread.
__global__ void __launch_bounds__(256, 4) sgemm_bias(
    const float* __restrict__ X, const float* __restrict__ W,
    const float* __restrict__ b, float* __restrict__ Y)
{
    __shared__ float Xs[16][65];   // [k][m] (transposed stage)
    __shared__ float Ws[16][65];   // [k][n]

    const int tid = threadIdx.x;
    const int tx = tid & 15;       // n direction
    const int ty = tid >> 4;       // m direction
    const int mBase = blockIdx.y * 64;
    const int nBase = blockIdx.x * 64;

    float acc[4][4] = {};

    for (int kt = 0; kt < D_MODEL; kt += 16) {
        #pragma unroll
        for (int i = 0; i < 4; i++) {
            int idx = tid + i * 256;           // 0..1023 over 64 rows x 16 k
            int r  = idx >> 4;
            int kk = idx & 15;
            Xs[kk][r] = X[(size_t)(mBase + r) * D_MODEL + kt + kk];
            Ws[kk][r] = W[(size_t)(nBase + r) * D_MODEL + kt + kk];
        }
        __syncthreads();
        #pragma unroll
        for (int kk = 0; kk < 16; kk++) {
            float xv[4], wv[4];
            #pragma unroll
            for (int i = 0; i < 4; i++) xv[i] = Xs[kk][ty * 4 + i];
            #pragma unroll
            for (int j = 0; j < 4; j++) wv[j] = Ws[kk][tx * 4 + j];
            #pragma unroll
            for (int i = 0; i < 4; i++)
                #pragma unroll
                for (int j = 0; j < 4; j++)
                    acc[i][j] += xv[i] * wv[j];
        }
        __syncthreads();
    }

    #pragma unroll
    for (int i = 0; i < 4; i++) {
        int m = mBase + ty * 4 + i;
        #pragma unroll
        for (int j = 0; j < 4; j++) {
            int n = nBase + tx * 4 + j;
            Y[(size_t)m * D_MODEL + n] = acc[i][j] + b[n];
        }
    }
}

// -------------------- Flash-style attention --------------------
// grid: (S/64, B*H). One CTA: 64 query rows for one (b,h). Online softmax over
// 32 key tiles of 64. Q,K staged dim-major (conflict-free QK^T), V key-major.
#define TQ 64
#define TK 64
#define SMEM_ATTN (4 * 64 * 68 * 4 + 3 * 64 * 4)

__global__ void __launch_bounds__(256) attn_kernel(
    const float* __restrict__ Q, const float* __restrict__ K,
    const float* __restrict__ V, float* __restrict__ O)
{
    const int bh = blockIdx.y;
    const int b = bh / N_HEADS, h = bh % N_HEADS;
    const int qBase = blockIdx.x * TQ;
    const size_t baseOff = (size_t)b * S_LEN * D_MODEL + (size_t)h * DK;

    extern __shared__ float sm[];
    float* Qst = sm;                 // [64 dims][68]  (dim-major)
    float* Kst = Qst + 64 * 68;      // [64 dims][68]
    float* Vs  = Kst + 64 * 68;      // [64 keys][68]  (key-major)
    float* Ss  = Vs  + 64 * 68;      // [64 q][68]
    float* row_m = Ss + 64 * 68;
    float* row_l = row_m + 64;
    float* row_a = row_l + 64;

    const int tid  = threadIdx.x;
    const int tx   = tid & 15;
    const int ty   = tid >> 4;
    const int lane = tid & 31;
    const int warp = tid >> 5;

    // load Q tile transposed (dim-major)
    #pragma unroll
    for (int i = 0; i < 4; i++) {
        int idx = tid + i * 256;             // over 64 rows x 16 float4
        int r  = idx >> 4;
        int c4 = (idx & 15) * 4;
        float4 v4 = *(const float4*)&Q[baseOff + (size_t)(qBase + r) * D_MODEL + c4];
        Qst[(c4 + 0) * 68 + r] = v4.x;
        Qst[(c4 + 1) * 68 + r] = v4.y;
        Qst[(c4 + 2) * 68 + r] = v4.z;
        Qst[(c4 + 3) * 68 + r] = v4.w;
    }
    if (tid < 64) { row_m[tid] = -1e30f; row_l[tid] = 0.0f; }

    float acc[4][4] = {};
    const float scale = 0.125f;   // 1/sqrt(64)

    for (int kv = 0; kv < S_LEN; kv += TK) {
        __syncthreads();   // protect Kst/Vs/Ss reuse (and Q/row_m init on iter 0)
        #pragma unroll
        for (int i = 0; i < 4; i++) {
            int idx = tid + i * 256;
            int r  = idx >> 4;
            int c4 = (idx & 15) * 4;
            float4 k4 = *(const float4*)&K[baseOff + (size_t)(kv + r) * D_MODEL + c4];
            Kst[(c4 + 0) * 68 + r] = k4.x;
            Kst[(c4 + 1) * 68 + r] = k4.y;
            Kst[(c4 + 2) * 68 + r] = k4.z;
            Kst[(c4 + 3) * 68 + r] = k4.w;
            float4 v4 = *(const float4*)&V[baseOff + (size_t)(kv + r) * D_MODEL + c4];
            *(float4*)&Vs[r * 68 + c4] = v4;
        }
        __syncthreads();

        // S = scale * Q K^T (4x4 per thread)
        float s[4][4] = {};
        #pragma unroll
        for (int d = 0; d < 64; d++) {
            float qv[4], kk[4];
            #pragma unroll
            for (int i = 0; i < 4; i++) qv[i] = Qst[d * 68 + ty * 4 + i];
            #pragma unroll
            for (int j = 0; j < 4; j++) kk[j] = Kst[d * 68 + tx * 4 + j];
            #pragma unroll
            for (int i = 0; i < 4; i++)
                #pragma unroll
                for (int j = 0; j < 4; j++)
                    s[i][j] += qv[i] * kk[j];
        }
        #pragma unroll
        for (int i = 0; i < 4; i++)
            #pragma unroll
            for (int j = 0; j < 4; j++)
                Ss[(ty * 4 + i) * 68 + tx * 4 + j] = s[i][j] * scale;
        __syncthreads();

        // online softmax: each warp owns 8 rows
        for (int rr = 0; rr < 8; rr++) {
            int r = warp * 8 + rr;
            float v0 = Ss[r * 68 + lane];
            float v1 = Ss[r * 68 + lane + 32];
            float mx = fmaxf(v0, v1);
            #pragma unroll
            for (int o = 16; o > 0; o >>= 1)
                mx = fmaxf(mx, __shfl_xor_sync(0xffffffffu, mx, o));
            float m_old = row_m[r];
            float m_new = fmaxf(m_old, mx);
            float p0 = __expf(v0 - m_new);
            float p1 = __expf(v1 - m_new);
            Ss[r * 68 + lane]      = p0;
            Ss[r * 68 + lane + 32] = p1;
            float sum = p0 + p1;
            #pragma unroll
            for (int o = 16; o > 0; o >>= 1)
                sum += __shfl_xor_sync(0xffffffffu, sum, o);
            if (lane == 0) {
                float alpha = __expf(m_old - m_new);
                row_a[r] = alpha;
                row_l[r] = row_l[r] * alpha + sum;
                row_m[r] = m_new;
            }
        }
        __syncthreads();

        // O = O*alpha + P @ V
        #pragma unroll
        for (int i = 0; i < 4; i++) {
            float a = row_a[ty * 4 + i];
            #pragma unroll
            for (int j = 0; j < 4; j++) acc[i][j] *= a;
        }
        #pragma unroll
        for (int k2 = 0; k2 < 64; k2++) {
            float pv[4], vv[4];
            #pragma unroll
            for (int i = 0; i < 4; i++) pv[i] = Ss[(ty * 4 + i) * 68 + k2];
            #pragma unroll
            for (int j = 0; j < 4; j++) vv[j] = Vs[k2 * 68 + tx * 4 + j];
            #pragma unroll
            for (int i = 0; i < 4; i++)
                #pragma unroll
                for (int j = 0; j < 4; j++)
                    acc[i][j] += pv[i] * vv[j];
        }
    }
    __syncthreads();

    // normalize + write back ([B,S,H,dk] -> concat is the natural layout)
    #pragma unroll
    for (int i = 0; i < 4; i++) {
        int r = ty * 4 + i;
        float inv = 1.0f / row_l[r];
        #pragma unroll
        for (int j = 0; j < 4; j++) {
            O[baseOff + (size_t)(qBase + r) * D_MODEL + tx * 4 + j] = acc[i][j] * inv;
        }
    }
}

// -------------------- launcher --------------------
extern "C" void kernel_launch(void* const* d_in, const int* in_sizes, int n_in,
                              void* d_out, int out_size)
{
    const float* q   = (const float*)d_in[0];
    const float* k   = (const float*)d_in[1];
    const float* v   = (const float*)d_in[2];
    const float* w_q = (const float*)d_in[3];
    const float* b_q = (const float*)d_in[4];
    const float* w_k = (const float*)d_in[5];
    const float* b_k = (const float*)d_in[6];
    const float* w_v = (const float*)d_in[7];
    const float* b_v = (const float*)d_in[8];
    const float* w_o = (const float*)d_in[9];
    const float* b_o = (const float*)d_in[10];
    float* out = (float*)d_out;

    float *Qp, *Kp, *Vp, *AOp;
    cudaGetSymbolAddress((void**)&Qp,  g_Q);
    cudaGetSymbolAddress((void**)&Kp,  g_K);
    cudaGetSymbolAddress((void**)&Vp,  g_V);
    cudaGetSymbolAddress((void**)&AOp, g_AO);

    cudaFuncSetAttribute(attn_kernel, cudaFuncAttributeMaxDynamicSharedMemorySize, SMEM_ATTN);

    dim3 gG(D_MODEL / 64, M_ROWS / 64);   // (16, 64)
    sgemm_bias<<<gG, 256>>>(q, w_q, b_q, Qp);
    sgemm_bias<<<gG, 256>>>(k, w_k, b_k, Kp);
    sgemm_bias<<<gG, 256>>>(v, w_v, b_v, Vp);

    dim3 gA(S_LEN / TQ, B_SZ * N_HEADS);  // (32, 32)
    attn_kernel<<<gA, 256, SMEM_ATTN>>>(Qp, Kp, Vp, AOp);

    sgemm_bias<<<gG, 256>>>(AOp, w_o, b_o, out);
}

// round 3
// speedup vs baseline: 1.7989x; 1.7989x over previous
#include <cuda_runtime.h>
#include <cuda_bf16.h>
#include <math.h>
#include <stdint.h>

#define D_MODEL 1024
#define N_HEADS 16
#define DK 64
#define B_SZ 2
#define S_LEN 2048
#define M_ROWS (B_SZ * S_LEN)   // 4096

// -------------------- scratch (allocation-free) --------------------
__device__ float g_Q[M_ROWS * D_MODEL];
__device__ float g_K[M_ROWS * D_MODEL];
__device__ float g_V[M_ROWS * D_MODEL];
__device__ float g_AO[M_ROWS * D_MODEL];

// ==================== helpers ====================
__device__ __forceinline__ uint32_t smem_to_u32(const void* p) {
    uint32_t a;
    asm("{ .reg .u64 t; cvta.to.shared.u64 t, %1; cvt.u32.u64 %0, t; }" : "=r"(a) : "l"(p));
    return a;
}

#define LDMAT4(r, addr) \
    asm volatile("ldmatrix.sync.aligned.m8n8.x4.shared.b16 {%0,%1,%2,%3}, [%4];" \
        : "=r"((r)[0]), "=r"((r)[1]), "=r"((r)[2]), "=r"((r)[3]) : "r"(addr))

__device__ __forceinline__ void mma16816(float* d, const uint32_t* a, const uint32_t* b) {
    asm volatile(
        "mma.sync.aligned.m16n8k16.row.col.f32.bf16.bf16.f32 "
        "{%0,%1,%2,%3},{%4,%5,%6,%7},{%8,%9},{%0,%1,%2,%3};"
        : "+f"(d[0]), "+f"(d[1]), "+f"(d[2]), "+f"(d[3])
        : "r"(a[0]), "r"(a[1]), "r"(a[2]), "r"(a[3]), "r"(b[0]), "r"(b[1]));
}

// split fp32x4 -> bf16 hi (8B) + bf16 lo (8B)
__device__ __forceinline__ void bf16x3_split(float4 v, uint2& hv, uint2& lv) {
    __nv_bfloat162 h01 = __float22bfloat162_rn(make_float2(v.x, v.y));
    __nv_bfloat162 h23 = __float22bfloat162_rn(make_float2(v.z, v.w));
    float2 f01 = __bfloat1622float2(h01);
    float2 f23 = __bfloat1622float2(h23);
    __nv_bfloat162 l01 = __float22bfloat162_rn(make_float2(v.x - f01.x, v.y - f01.y));
    __nv_bfloat162 l23 = __float22bfloat162_rn(make_float2(v.z - f23.x, v.w - f23.y));
    hv.x = *(uint32_t*)&h01; hv.y = *(uint32_t*)&h23;
    lv.x = *(uint32_t*)&l01; lv.y = *(uint32_t*)&l23;
}

// ==================== mma.sync bf16x3 GEMM ====================
// Y[M,N] = X[M,K] @ W[N,K]^T + bias[N];  M=4096, N=K=1024.
// CTA 128x128, BK=32, 8 warps (4M x 2N), warp tile 32x64, double-buffered smem.
// smem tiles at 80B row stride (perfect 16B-slot permutation -> conflict-free ldmatrix).

#define BK 32
#define ROW_B 80                      // bytes per smem row (32 bf16 + 8 pad)
#define TILE_SB (128 * ROW_B)         // 10240 B per tile
#define BUF_SB (4 * TILE_SB)          // Ah, Al, Bh, Bl = 40960 B
#define GEMM_SMEM (2 * BUF_SB)        // 81920 B

__global__ void __launch_bounds__(256) gemm_mma(
    const float* __restrict__ X, const float* __restrict__ W,
    const float* __restrict__ bias, float* __restrict__ Y)
{
    extern __shared__ char sm[];
    const uint32_t sbase = smem_to_u32(sm);

    const int tid   = threadIdx.x;
    const int lane  = tid & 31;
    const int wid   = tid >> 5;
    const int warpM = wid & 3;    // 0..3 -> 32-row slice
    const int warpN = wid >> 2;   // 0..1 -> 64-col slice
    const int mBase = blockIdx.y * 128;
    const int nBase = blockIdx.x * 128;

    // ldmatrix per-thread offsets
    // A frag (m16k16 x4): lanes0-15 rows0-15 k0, lanes16-31 rows0-15 k8
    const uint32_t aOff = (uint32_t)(warpM * 32 + (lane & 15)) * ROW_B + (uint32_t)(lane >> 4) * 16;
    // B frag pair (two n8k16 via x4): lanes0-7 n0-7 k0, 8-15 n0-7 k8, 16-23 n8-15 k0, 24-31 n8-15 k8
    const uint32_t bOff = (uint32_t)(warpN * 64 + (lane & 7) + ((lane >> 4) & 1) * 8) * ROW_B
                        + (uint32_t)((lane >> 3) & 1) * 16;

    // global load mapping: 128 rows x 8 float4-cols, 4 iters of 256 threads
    const int gr  = (tid + 0) >> 3;          // pattern per iter: r = (tid + i*256)>>3
    const int gc4 = (tid & 7) * 4;
    const uint32_t stsOff = (uint32_t)gr * ROW_B + (uint32_t)gc4 * 2;

    const float* Xg = X + (size_t)mBase * D_MODEL;
    const float* Wg = W + (size_t)nBase * D_MODEL;

    float acc[2][8][4] = {};

    // bias per output fragment column
    float2 bv[8];
    #pragma unroll
    for (int ni = 0; ni < 8; ni++)
        bv[ni] = *(const float2*)&bias[nBase + warpN * 64 + ni * 8 + (lane & 3) * 2];

    // ---- prologue: stage chunk 0 into buf 0 ----
    {
        char* buf = sm;
        #pragma unroll
        for (int i = 0; i < 4; i++) {
            int r = gr + i * 32;
            uint32_t so = stsOff + (uint32_t)i * 32 * ROW_B;
            float4 xv = *(const float4*)(Xg + (size_t)r * D_MODEL + gc4);
            uint2 hv, lv; bf16x3_split(xv, hv, lv);
            *(uint2*)(buf + 0 * TILE_SB + so) = hv;
            *(uint2*)(buf + 1 * TILE_SB + so) = lv;
            float4 wv = *(const float4*)(Wg + (size_t)r * D_MODEL + gc4);
            bf16x3_split(wv, hv, lv);
            *(uint2*)(buf + 2 * TILE_SB + so) = hv;
            *(uint2*)(buf + 3 * TILE_SB + so) = lv;
        }
    }
    __syncthreads();

    const int NCH = D_MODEL / BK;   // 32
    for (int ch = 0; ch < NCH; ch++) {
        const int cur = ch & 1;

        // prefetch next chunk to registers
        float4 xr[4], wr[4];
        if (ch + 1 < NCH) {
            const int kt = (ch + 1) * BK;
            #pragma unroll
            for (int i = 0; i < 4; i++) {
                int r = gr + i * 32;
                xr[i] = *(const float4*)(Xg + (size_t)r * D_MODEL + kt + gc4);
                wr[i] = *(const float4*)(Wg + (size_t)r * D_MODEL + kt + gc4);
            }
        }

        // compute on current buffer
        const uint32_t aHi = sbase + (uint32_t)cur * BUF_SB + aOff;
        const uint32_t aLo = aHi + TILE_SB;
        const uint32_t bHi = sbase + (uint32_t)cur * BUF_SB + 2 * TILE_SB + bOff;
        const uint32_t bLo = bHi + TILE_SB;

        #pragma unroll
        for (int ks = 0; ks < 2; ks++) {
            uint32_t ah[2][4], al[2][4], bh[4][4], bl[4][4];
            LDMAT4(ah[0], aHi + ks * 32);
            LDMAT4(ah[1], aHi + 16 * ROW_B + ks * 32);
            LDMAT4(al[0], aLo + ks * 32);
            LDMAT4(al[1], aLo + 16 * ROW_B + ks * 32);
            #pragma unroll
            for (int p = 0; p < 4; p++) {
                LDMAT4(bh[p], bHi + (uint32_t)p * 16 * ROW_B + ks * 32);
                LDMAT4(bl[p], bLo + (uint32_t)p * 16 * ROW_B + ks * 32);
            }
            #pragma unroll
            for (int mi = 0; mi < 2; mi++) {
                #pragma unroll
                for (int p = 0; p < 4; p++) {
                    mma16816(acc[mi][2 * p + 0], ah[mi], &bh[p][0]);
                    mma16816(acc[mi][2 * p + 1], ah[mi], &bh[p][2]);
                    mma16816(acc[mi][2 * p + 0], ah[mi], &bl[p][0]);
                    mma16816(acc[mi][2 * p + 1], ah[mi], &bl[p][2]);
                    mma16816(acc[mi][2 * p + 0], al[mi], &bh[p][0]);
                    mma16816(acc[mi][2 * p + 1], al[mi], &bh[p][2]);
                }
            }
        }

        // stage next chunk into the other buffer
        if (ch + 1 < NCH) {
            char* buf = sm + (cur ^ 1) * BUF_SB;
            #pragma unroll
            for (int i = 0; i < 4; i++) {
                uint32_t so = stsOff + (uint32_t)i * 32 * ROW_B;
                uint2 hv, lv;
                bf16x3_split(xr[i], hv, lv);
                *(uint2*)(buf + 0 * TILE_SB + so) = hv;
                *(uint2*)(buf + 1 * TILE_SB + so) = lv;
                bf16x3_split(wr[i], hv, lv);
                *(uint2*)(buf + 2 * TILE_SB + so) = hv;
                *(uint2*)(buf + 3 * TILE_SB + so) = lv;
            }
        }
        __syncthreads();
    }

    // ---- epilogue: write acc + bias ----
    #pragma unroll
    for (int mi = 0; mi < 2; mi++) {
        const int row0 = mBase + warpM * 32 + mi * 16 + (lane >> 2);
        #pragma unroll
        for (int ni = 0; ni < 8; ni++) {
            const int col = nBase + warpN * 64 + ni * 8 + (lane & 3) * 2;
            float2 o0, o1;
            o0.x = acc[mi][ni][0] + bv[ni].x;
            o0.y = acc[mi][ni][1] + bv[ni].y;
            o1.x = acc[mi][ni][2] + bv[ni].x;
            o1.y = acc[mi][ni][3] + bv[ni].y;
            *(float2*)&Y[(size_t)row0 * D_MODEL + col]       = o0;
            *(float2*)&Y[(size_t)(row0 + 8) * D_MODEL + col] = o1;
        }
    }
}

// -------------------- Flash-style attention (unchanged fp32, known-good) --------------------
#define TQ 64
#define TK 64
#define SMEM_ATTN (4 * 64 * 68 * 4 + 3 * 64 * 4)

__global__ void __launch_bounds__(256) attn_kernel(
    const float* __restrict__ Q, const float* __restrict__ K,
    const float* __restrict__ V, float* __restrict__ O)
{
    const int bh = blockIdx.y;
    const int b = bh / N_HEADS, h = bh % N_HEADS;
    const int qBase = blockIdx.x * TQ;
    const size_t baseOff = (size_t)b * S_LEN * D_MODEL + (size_t)h * DK;

    extern __shared__ float smf[];
    float* Qst = smf;
    float* Kst = Qst + 64 * 68;
    float* Vs  = Kst + 64 * 68;
    float* Ss  = Vs  + 64 * 68;
    float* row_m = Ss + 64 * 68;
    float* row_l = row_m + 64;
    float* row_a = row_l + 64;

    const int tid  = threadIdx.x;
    const int tx   = tid & 15;
    const int ty   = tid >> 4;
    const int lane = tid & 31;
    const int warp = tid >> 5;

    #pragma unroll
    for (int i = 0; i < 4; i++) {
        int idx = tid + i * 256;
        int r  = idx >> 4;
        int c4 = (idx & 15) * 4;
        float4 v4 = *(const float4*)&Q[baseOff + (size_t)(qBase + r) * D_MODEL + c4];
        Qst[(c4 + 0) * 68 + r] = v4.x;
        Qst[(c4 + 1) * 68 + r] = v4.y;
        Qst[(c4 + 2) * 68 + r] = v4.z;
        Qst[(c4 + 3) * 68 + r] = v4.w;
    }
    if (tid < 64) { row_m[tid] = -1e30f; row_l[tid] = 0.0f; }

    float acc[4][4] = {};
    const float scale = 0.125f;

    for (int kv = 0; kv < S_LEN; kv += TK) {
        __syncthreads();
        #pragma unroll
        for (int i = 0; i < 4; i++) {
            int idx = tid + i * 256;
            int r  = idx >> 4;
            int c4 = (idx & 15) * 4;
            float4 k4 = *(const float4*)&K[baseOff + (size_t)(kv + r) * D_MODEL + c4];
            Kst[(c4 + 0) * 68 + r] = k4.x;
            Kst[(c4 + 1) * 68 + r] = k4.y;
            Kst[(c4 + 2) * 68 + r] = k4.z;
            Kst[(c4 + 3) * 68 + r] = k4.w;
            float4 v4 = *(const float4*)&V[baseOff + (size_t)(kv + r) * D_MODEL + c4];
            *(float4*)&Vs[r * 68 + c4] = v4;
        }
        __syncthreads();

        float s[4][4] = {};
        #pragma unroll
        for (int d = 0; d < 64; d++) {
            float qv[4], kk[4];
            #pragma unroll
            for (int i = 0; i < 4; i++) qv[i] = Qst[d * 68 + ty * 4 + i];
            #pragma unroll
            for (int j = 0; j < 4; j++) kk[j] = Kst[d * 68 + tx * 4 + j];
            #pragma unroll
            for (int i = 0; i < 4; i++)
                #pragma unroll
                for (int j = 0; j < 4; j++)
                    s[i][j] += qv[i] * kk[j];
        }
        #pragma unroll
        for (int i = 0; i < 4; i++)
            #pragma unroll
            for (int j = 0; j < 4; j++)
                Ss[(ty * 4 + i) * 68 + tx * 4 + j] = s[i][j] * scale;
        __syncthreads();

        for (int rr = 0; rr < 8; rr++) {
            int r = warp * 8 + rr;
            float v0 = Ss[r * 68 + lane];
            float v1 = Ss[r * 68 + lane + 32];
            float mx = fmaxf(v0, v1);
            #pragma unroll
            for (int o = 16; o > 0; o >>= 1)
                mx = fmaxf(mx, __shfl_xor_sync(0xffffffffu, mx, o));
            float m_old = row_m[r];
            float m_new = fmaxf(m_old, mx);
            float p0 = __expf(v0 - m_new);
            float p1 = __expf(v1 - m_new);
            Ss[r * 68 + lane]      = p0;
            Ss[r * 68 + lane + 32] = p1;
            float sum = p0 + p1;
            #pragma unroll
            for (int o = 16; o > 0; o >>= 1)
                sum += __shfl_xor_sync(0xffffffffu, sum, o);
            if (lane == 0) {
                float alpha = __expf(m_old - m_new);
                row_a[r] = alpha;
                row_l[r] = row_l[r] * alpha + sum;
                row_m[r] = m_new;
            }
        }
        __syncthreads();

        #pragma unroll
        for (int i = 0; i < 4; i++) {
            float a = row_a[ty * 4 + i];
            #pragma unroll
            for (int j = 0; j < 4; j++) acc[i][j] *= a;
        }
        #pragma unroll
        for (int k2 = 0; k2 < 64; k2++) {
            float pv[4], vv[4];
            #pragma unroll
            for (int i = 0; i < 4; i++) pv[i] = Ss[(ty * 4 + i) * 68 + k2];
            #pragma unroll
            for (int j = 0; j < 4; j++) vv[j] = Vs[k2 * 68 + tx * 4 + j];
            #pragma unroll
            for (int i = 0; i < 4; i++)
                #pragma unroll
                for (int j = 0; j < 4; j++)
                    acc[i][j] += pv[i] * vv[j];
        }
    }
    __syncthreads();

    #pragma unroll
    for (int i = 0; i < 4; i++) {
        int r = ty * 4 + i;
        float inv = 1.0f / row_l[r];
        #pragma unroll
        for (int j = 0; j < 4; j++) {
            O[baseOff + (size_t)(qBase + r) * D_MODEL + tx * 4 + j] = acc[i][j] * inv;
        }
    }
}

// -------------------- launcher --------------------
extern "C" void kernel_launch(void* const* d_in, const int* in_sizes, int n_in,
                              void* d_out, int out_size)
{
    const float* q   = (const float*)d_in[0];
    const float* k   = (const float*)d_in[1];
    const float* v   = (const float*)d_in[2];
    const float* w_q = (const float*)d_in[3];
    const float* b_q = (const float*)d_in[4];
    const float* w_k = (const float*)d_in[5];
    const float* b_k = (const float*)d_in[6];
    const float* w_v = (const float*)d_in[7];
    const float* b_v = (const float*)d_in[8];
    const float* w_o = (const float*)d_in[9];
    const float* b_o = (const float*)d_in[10];
    float* out = (float*)d_out;

    float *Qp, *Kp, *Vp, *AOp;
    cudaGetSymbolAddress((void**)&Qp,  g_Q);
    cudaGetSymbolAddress((void**)&Kp,  g_K);
    cudaGetSymbolAddress((void**)&Vp,  g_V);
    cudaGetSymbolAddress((void**)&AOp, g_AO);

    cudaFuncSetAttribute(gemm_mma, cudaFuncAttributeMaxDynamicSharedMemorySize, GEMM_SMEM);
    cudaFuncSetAttribute(attn_kernel, cudaFuncAttributeMaxDynamicSharedMemorySize, SMEM_ATTN);

    dim3 gG(D_MODEL / 128, M_ROWS / 128);   // (8, 32)
    gemm_mma<<<gG, 256, GEMM_SMEM>>>(q, w_q, b_q, Qp);
    gemm_mma<<<gG, 256, GEMM_SMEM>>>(k, w_k, b_k, Kp);
    gemm_mma<<<gG, 256, GEMM_SMEM>>>(v, w_v, b_v, Vp);

    dim3 gA(S_LEN / TQ, B_SZ * N_HEADS);  // (32, 32)
    attn_kernel<<<gA, 256, SMEM_ATTN>>>(Qp, Kp, Vp, AOp);

    gemm_mma<<<gG, 256, GEMM_SMEM>>>(AOp, w_o, b_o, out);
}

// round 4
// speedup vs baseline: 4.0700x; 2.2625x over previous
#include <cuda_runtime.h>
#include <cuda_bf16.h>
#include <math.h>
#include <stdint.h>

#define D_MODEL 1024
#define N_HEADS 16
#define DK 64
#define B_SZ 2
#define S_LEN 2048
#define M_ROWS (B_SZ * S_LEN)   // 4096

// -------------------- scratch (allocation-free) --------------------
__device__ __nv_bfloat16 g_Qh[M_ROWS * D_MODEL];
__device__ __nv_bfloat16 g_Ql[M_ROWS * D_MODEL];
__device__ __nv_bfloat16 g_Kh[M_ROWS * D_MODEL];
__device__ __nv_bfloat16 g_Kl[M_ROWS * D_MODEL];
__device__ __nv_bfloat16 g_Vh[M_ROWS * D_MODEL];
__device__ __nv_bfloat16 g_Vl[M_ROWS * D_MODEL];
__device__ float g_AO[M_ROWS * D_MODEL];

// ==================== helpers ====================
__device__ __forceinline__ uint32_t smem_to_u32(const void* p) {
    uint32_t a;
    asm("{ .reg .u64 t; cvta.to.shared.u64 t, %1; cvt.u32.u64 %0, t; }" : "=r"(a) : "l"(p));
    return a;
}

#define LDMAT4(r, addr) \
    asm volatile("ldmatrix.sync.aligned.m8n8.x4.shared.b16 {%0,%1,%2,%3}, [%4];" \
        : "=r"((r)[0]), "=r"((r)[1]), "=r"((r)[2]), "=r"((r)[3]) : "r"(addr))

#define LDMAT4T(r, addr) \
    asm volatile("ldmatrix.sync.aligned.m8n8.x4.trans.shared.b16 {%0,%1,%2,%3}, [%4];" \
        : "=r"((r)[0]), "=r"((r)[1]), "=r"((r)[2]), "=r"((r)[3]) : "r"(addr))

__device__ __forceinline__ void mma16816(float* d, const uint32_t* a, const uint32_t* b) {
    asm volatile(
        "mma.sync.aligned.m16n8k16.row.col.f32.bf16.bf16.f32 "
        "{%0,%1,%2,%3},{%4,%5,%6,%7},{%8,%9},{%0,%1,%2,%3};"
        : "+f"(d[0]), "+f"(d[1]), "+f"(d[2]), "+f"(d[3])
        : "r"(a[0]), "r"(a[1]), "r"(a[2]), "r"(a[3]), "r"(b[0]), "r"(b[1]));
}

__device__ __forceinline__ void cp16(uint32_t dst, const void* src) {
    asm volatile("cp.async.ca.shared.global [%0], [%1], 16;" :: "r"(dst), "l"(src) : "memory");
}
#define CP_COMMIT() asm volatile("cp.async.commit_group;" ::: "memory")
#define CP_WAIT(n)  asm volatile("cp.async.wait_group %0;" :: "n"(n) : "memory")

__device__ __forceinline__ uint32_t pack_hi(float a, float b) {
    __nv_bfloat162 t = __float22bfloat162_rn(make_float2(a, b));
    return *(uint32_t*)&t;
}
__device__ __forceinline__ uint32_t pack_lo(float a, float b, uint32_t hi) {
    __nv_bfloat162 h = *(__nv_bfloat162*)&hi;
    float2 f = __bfloat1622float2(h);
    __nv_bfloat162 t = __float22bfloat162_rn(make_float2(a - f.x, b - f.y));
    return *(uint32_t*)&t;
}

// split fp32x4 -> bf16 hi (8B) + bf16 lo (8B)
__device__ __forceinline__ void bf16x3_split(float4 v, uint2& hv, uint2& lv) {
    __nv_bfloat162 h01 = __float22bfloat162_rn(make_float2(v.x, v.y));
    __nv_bfloat162 h23 = __float22bfloat162_rn(make_float2(v.z, v.w));
    float2 f01 = __bfloat1622float2(h01);
    float2 f23 = __bfloat1622float2(h23);
    __nv_bfloat162 l01 = __float22bfloat162_rn(make_float2(v.x - f01.x, v.y - f01.y));
    __nv_bfloat162 l23 = __float22bfloat162_rn(make_float2(v.z - f23.x, v.w - f23.y));
    hv.x = *(uint32_t*)&h01; hv.y = *(uint32_t*)&h23;
    lv.x = *(uint32_t*)&l01; lv.y = *(uint32_t*)&l23;
}

// ==================== mma.sync bf16x3 GEMM ====================
// Y[M,N] = X[M,K] @ W[N,K]^T + bias[N];  M=4096, N=K=1024.
// BF16OUT: write bf16 hi/lo decomposition instead of fp32.
#define BK 32
#define ROW_B 80
#define TILE_SB (128 * ROW_B)
#define BUF_SB (4 * TILE_SB)
#define GEMM_SMEM (2 * BUF_SB)        // 81920 B

template <bool BF16OUT>
__global__ void __launch_bounds__(256) gemm_mma(
    const float* __restrict__ X, const float* __restrict__ W,
    const float* __restrict__ bias, float* __restrict__ Y,
    __nv_bfloat16* __restrict__ Yh, __nv_bfloat16* __restrict__ Yl)
{
    extern __shared__ char sm[];
    const uint32_t sbase = smem_to_u32(sm);

    const int tid   = threadIdx.x;
    const int lane  = tid & 31;
    const int wid   = tid >> 5;
    const int warpM = wid & 3;
    const int warpN = wid >> 2;
    const int mBase = blockIdx.y * 128;
    const int nBase = blockIdx.x * 128;

    const uint32_t aOff = (uint32_t)(warpM * 32 + (lane & 15)) * ROW_B + (uint32_t)(lane >> 4) * 16;
    const uint32_t bOff = (uint32_t)(warpN * 64 + (lane & 7) + ((lane >> 4) & 1) * 8) * ROW_B
                        + (uint32_t)((lane >> 3) & 1) * 16;

    const int gr  = tid >> 3;
    const int gc4 = (tid & 7) * 4;
    const uint32_t stsOff = (uint32_t)gr * ROW_B + (uint32_t)gc4 * 2;

    const float* Xg = X + (size_t)mBase * D_MODEL;
    const float* Wg = W + (size_t)nBase * D_MODEL;

    float acc[2][8][4] = {};

    float2 bv[8];
    #pragma unroll
    for (int ni = 0; ni < 8; ni++)
        bv[ni] = *(const float2*)&bias[nBase + warpN * 64 + ni * 8 + (lane & 3) * 2];

    {
        char* buf = sm;
        #pragma unroll
        for (int i = 0; i < 4; i++) {
            int r = gr + i * 32;
            uint32_t so = stsOff + (uint32_t)i * 32 * ROW_B;
            float4 xv = *(const float4*)(Xg + (size_t)r * D_MODEL + gc4);
            uint2 hv, lv; bf16x3_split(xv, hv, lv);
            *(uint2*)(buf + 0 * TILE_SB + so) = hv;
            *(uint2*)(buf + 1 * TILE_SB + so) = lv;
            float4 wv = *(const float4*)(Wg + (size_t)r * D_MODEL + gc4);
            bf16x3_split(wv, hv, lv);
            *(uint2*)(buf + 2 * TILE_SB + so) = hv;
            *(uint2*)(buf + 3 * TILE_SB + so) = lv;
        }
    }
    __syncthreads();

    const int NCH = D_MODEL / BK;
    for (int ch = 0; ch < NCH; ch++) {
        const int cur = ch & 1;

        float4 xr[4], wr[4];
        if (ch + 1 < NCH) {
            const int kt = (ch + 1) * BK;
            #pragma unroll
            for (int i = 0; i < 4; i++) {
                int r = gr + i * 32;
                xr[i] = *(const float4*)(Xg + (size_t)r * D_MODEL + kt + gc4);
                wr[i] = *(const float4*)(Wg + (size_t)r * D_MODEL + kt + gc4);
            }
        }

        const uint32_t aHi = sbase + (uint32_t)cur * BUF_SB + aOff;
        const uint32_t aLo = aHi + TILE_SB;
        const uint32_t bHi = sbase + (uint32_t)cur * BUF_SB + 2 * TILE_SB + bOff;
        const uint32_t bLo = bHi + TILE_SB;

        #pragma unroll
        for (int ks = 0; ks < 2; ks++) {
            uint32_t ah[2][4], al[2][4], bh[4][4], bl[4][4];
            LDMAT4(ah[0], aHi + ks * 32);
            LDMAT4(ah[1], aHi + 16 * ROW_B + ks * 32);
            LDMAT4(al[0], aLo + ks * 32);
            LDMAT4(al[1], aLo + 16 * ROW_B + ks * 32);
            #pragma unroll
            for (int p = 0; p < 4; p++) {
                LDMAT4(bh[p], bHi + (uint32_t)p * 16 * ROW_B + ks * 32);
                LDMAT4(bl[p], bLo + (uint32_t)p * 16 * ROW_B + ks * 32);
            }
            #pragma unroll
            for (int mi = 0; mi < 2; mi++) {
                #pragma unroll
                for (int p = 0; p < 4; p++) {
                    mma16816(acc[mi][2 * p + 0], ah[mi], &bh[p][0]);
                    mma16816(acc[mi][2 * p + 1], ah[mi], &bh[p][2]);
                    mma16816(acc[mi][2 * p + 0], ah[mi], &bl[p][0]);
                    mma16816(acc[mi][2 * p + 1], ah[mi], &bl[p][2]);
                    mma16816(acc[mi][2 * p + 0], al[mi], &bh[p][0]);
                    mma16816(acc[mi][2 * p + 1], al[mi], &bh[p][2]);
                }
            }
        }

        if (ch + 1 < NCH) {
            char* buf = sm + (cur ^ 1) * BUF_SB;
            #pragma unroll
            for (int i = 0; i < 4; i++) {
                uint32_t so = stsOff + (uint32_t)i * 32 * ROW_B;
                uint2 hv, lv;
                bf16x3_split(xr[i], hv, lv);
                *(uint2*)(buf + 0 * TILE_SB + so) = hv;
                *(uint2*)(buf + 1 * TILE_SB + so) = lv;
                bf16x3_split(wr[i], hv, lv);
                *(uint2*)(buf + 2 * TILE_SB + so) = hv;
                *(uint2*)(buf + 3 * TILE_SB + so) = lv;
            }
        }
        __syncthreads();
    }

    #pragma unroll
    for (int mi = 0; mi < 2; mi++) {
        const int row0 = mBase + warpM * 32 + mi * 16 + (lane >> 2);
        #pragma unroll
        for (int ni = 0; ni < 8; ni++) {
            const int col = nBase + warpN * 64 + ni * 8 + (lane & 3) * 2;
            float y00 = acc[mi][ni][0] + bv[ni].x;
            float y01 = acc[mi][ni][1] + bv[ni].y;
            float y10 = acc[mi][ni][2] + bv[ni].x;
            float y11 = acc[mi][ni][3] + bv[ni].y;
            if (BF16OUT) {
                uint32_t h0 = pack_hi(y00, y01);
                uint32_t l0 = pack_lo(y00, y01, h0);
                uint32_t h1 = pack_hi(y10, y11);
                uint32_t l1 = pack_lo(y10, y11, h1);
                *(uint32_t*)&Yh[(size_t)row0 * D_MODEL + col]       = h0;
                *(uint32_t*)&Yl[(size_t)row0 * D_MODEL + col]       = l0;
                *(uint32_t*)&Yh[(size_t)(row0 + 8) * D_MODEL + col] = h1;
                *(uint32_t*)&Yl[(size_t)(row0 + 8) * D_MODEL + col] = l1;
            } else {
                *(float2*)&Y[(size_t)row0 * D_MODEL + col]       = make_float2(y00, y01);
                *(float2*)&Y[(size_t)(row0 + 8) * D_MODEL + col] = make_float2(y10, y11);
            }
        }
    }
}

// ==================== tensor-core flash attention (bf16x3) ====================
// CTA: 128 q-rows of one (b,h). 8 warps x 16 q-rows, full 128-key tiles.
// S = Qh*Kh + Qh*Kl + Ql*Kh (fp32 acc); P split hi/lo; O += Ph*Vh + Ph*Vl + Pl*Vh.
#define AROW 144                      // 64 bf16 (128B) + 16B pad, odd 16B-slot stride
#define QTILE (128 * AROW)            // 18432
#define KVBUF (4 * QTILE)             // Kh,Kl,Vh,Vl = 73728
#define ATTN_SMEM (2 * QTILE + 2 * KVBUF)   // 184320

__global__ void __launch_bounds__(256) attn_tc(
    const __nv_bfloat16* __restrict__ Qh, const __nv_bfloat16* __restrict__ Ql,
    const __nv_bfloat16* __restrict__ Kh, const __nv_bfloat16* __restrict__ Kl,
    const __nv_bfloat16* __restrict__ Vh, const __nv_bfloat16* __restrict__ Vl,
    float* __restrict__ O)
{
    extern __shared__ char sm[];
    const uint32_t sbase = smem_to_u32(sm);

    const int tid  = threadIdx.x;
    const int lane = tid & 31;
    const int wid  = tid >> 5;
    const int bh = blockIdx.y;
    const int b = bh >> 4, h = bh & 15;
    const int qBase = blockIdx.x * 128;

    const size_t gOff = (size_t)b * S_LEN * D_MODEL + (size_t)h * DK;   // element offset

    const uint32_t sQh = sbase;
    const uint32_t sQl = sbase + QTILE;
    const uint32_t sKV0 = sbase + 2 * QTILE;

    // ---- issue Q + KV tile 0 (group 0) ----
    {
        const int r = tid >> 3;          // row 0..31 per iter (x4)
        const int c = tid & 7;           // 16B chunk
        #pragma unroll
        for (int i = 0; i < 4; i++) {
            int rr = r + i * 32;
            uint32_t dofs = (uint32_t)rr * AROW + (uint32_t)c * 16;
            size_t so = gOff + (size_t)(qBase + rr) * D_MODEL + c * 8;
            cp16(sQh + dofs, Qh + so);
            cp16(sQl + dofs, Ql + so);
            size_t sk = gOff + (size_t)rr * D_MODEL + c * 8;   // kv tile 0
            cp16(sKV0 + 0 * QTILE + dofs, Kh + sk);
            cp16(sKV0 + 1 * QTILE + dofs, Kl + sk);
            cp16(sKV0 + 2 * QTILE + dofs, Vh + sk);
            cp16(sKV0 + 3 * QTILE + dofs, Vl + sk);
        }
        CP_COMMIT();
    }

    // per-thread softmax state (rows r0 = lane>>2, r1 = r0+8 within warp's 16 rows)
    float m0 = -1e30f, m1 = -1e30f, l0 = 0.0f, l1 = 0.0f;
    float o[8][4] = {};
    const float scale = 0.125f;

    const uint32_t aOffQ = (uint32_t)(wid * 16 + (lane & 15)) * AROW + (uint32_t)(lane >> 4) * 16;
    const uint32_t bOffK = (uint32_t)((lane & 7) + ((lane >> 4) & 1) * 8) * AROW
                         + (uint32_t)((lane >> 3) & 1) * 16;
    const uint32_t vLaneRow = (uint32_t)((lane & 7) + ((lane >> 3) & 1) * 8);
    const uint32_t vLaneCol = (uint32_t)(lane >> 4) * 8;   // n or n+8 (bf16 elems)

    const int NT = S_LEN / 128;   // 16
    for (int t = 0; t < NT; t++) {
        const uint32_t cur = sKV0 + (uint32_t)(t & 1) * KVBUF;

        // prefetch next KV tile into other buffer
        if (t + 1 < NT) {
            const uint32_t nxt = sKV0 + (uint32_t)((t + 1) & 1) * KVBUF;
            const int r = tid >> 3;
            const int c = tid & 7;
            #pragma unroll
            for (int i = 0; i < 4; i++) {
                int rr = r + i * 32;
                uint32_t dofs = (uint32_t)rr * AROW + (uint32_t)c * 16;
                size_t sk = gOff + (size_t)((t + 1) * 128 + rr) * D_MODEL + c * 8;
                cp16(nxt + 0 * QTILE + dofs, Kh + sk);
                cp16(nxt + 1 * QTILE + dofs, Kl + sk);
                cp16(nxt + 2 * QTILE + dofs, Vh + sk);
                cp16(nxt + 3 * QTILE + dofs, Vl + sk);
            }
            CP_COMMIT();
            CP_WAIT(1);
        } else {
            CP_WAIT(0);
        }
        __syncthreads();

        // Q fragments (resident smem; reload per tile to ease register pressure)
        uint32_t qh[4][4], ql[4][4];
        #pragma unroll
        for (int ks = 0; ks < 4; ks++) {
            LDMAT4(qh[ks], sQh + aOffQ + ks * 32);
            LDMAT4(ql[ks], sQl + aOffQ + ks * 32);
        }

        // ---- S = Q K^T ----
        float s[16][4] = {};
        #pragma unroll
        for (int p = 0; p < 8; p++) {
            const uint32_t kb = cur + (uint32_t)p * 16 * AROW + bOffK;
            #pragma unroll
            for (int ks = 0; ks < 4; ks++) {
                uint32_t kh4[4], kl4[4];
                LDMAT4(kh4, kb + ks * 32);
                LDMAT4(kl4, kb + QTILE + ks * 32);
                mma16816(s[2 * p + 0], qh[ks], &kh4[0]);
                mma16816(s[2 * p + 1], qh[ks], &kh4[2]);
                mma16816(s[2 * p + 0], qh[ks], &kl4[0]);
                mma16816(s[2 * p + 1], qh[ks], &kl4[2]);
                mma16816(s[2 * p + 0], ql[ks], &kh4[0]);
                mma16816(s[2 * p + 1], ql[ks], &kh4[2]);
            }
        }

        // ---- online softmax ----
        float mx0 = -1e30f, mx1 = -1e30f;
        #pragma unroll
        for (int f = 0; f < 16; f++) {
            mx0 = fmaxf(mx0, fmaxf(s[f][0], s[f][1]));
            mx1 = fmaxf(mx1, fmaxf(s[f][2], s[f][3]));
        }
        mx0 = fmaxf(mx0, __shfl_xor_sync(0xffffffffu, mx0, 1));
        mx0 = fmaxf(mx0, __shfl_xor_sync(0xffffffffu, mx0, 2));
        mx1 = fmaxf(mx1, __shfl_xor_sync(0xffffffffu, mx1, 1));
        mx1 = fmaxf(mx1, __shfl_xor_sync(0xffffffffu, mx1, 2));

        float mn0 = fmaxf(m0, mx0 * scale);
        float mn1 = fmaxf(m1, mx1 * scale);
        float al0 = __expf(m0 - mn0);
        float al1 = __expf(m1 - mn1);
        m0 = mn0; m1 = mn1;

        float ls0 = 0.0f, ls1 = 0.0f;
        #pragma unroll
        for (int f = 0; f < 16; f++) {
            float p0 = __expf(fmaf(s[f][0], scale, -m0));
            float p1 = __expf(fmaf(s[f][1], scale, -m0));
            float p2 = __expf(fmaf(s[f][2], scale, -m1));
            float p3 = __expf(fmaf(s[f][3], scale, -m1));
            s[f][0] = p0; s[f][1] = p1; s[f][2] = p2; s[f][3] = p3;
            ls0 += p0 + p1;
            ls1 += p2 + p3;
        }
        ls0 += __shfl_xor_sync(0xffffffffu, ls0, 1);
        ls0 += __shfl_xor_sync(0xffffffffu, ls0, 2);
        ls1 += __shfl_xor_sync(0xffffffffu, ls1, 1);
        ls1 += __shfl_xor_sync(0xffffffffu, ls1, 2);
        l0 = l0 * al0 + ls0;
        l1 = l1 * al1 + ls1;

        #pragma unroll
        for (int nb = 0; nb < 8; nb++) {
            o[nb][0] *= al0; o[nb][1] *= al0;
            o[nb][2] *= al1; o[nb][3] *= al1;
        }

        // ---- O += P V ----
        #pragma unroll
        for (int fp = 0; fp < 8; fp++) {
            uint32_t ah[4], alr[4];
            ah[0]  = pack_hi(s[2*fp][0],   s[2*fp][1]);
            ah[1]  = pack_hi(s[2*fp][2],   s[2*fp][3]);
            ah[2]  = pack_hi(s[2*fp+1][0], s[2*fp+1][1]);
            ah[3]  = pack_hi(s[2*fp+1][2], s[2*fp+1][3]);
            alr[0] = pack_lo(s[2*fp][0],   s[2*fp][1],   ah[0]);
            alr[1] = pack_lo(s[2*fp][2],   s[2*fp][3],   ah[1]);
            alr[2] = pack_lo(s[2*fp+1][0], s[2*fp+1][1], ah[2]);
            alr[3] = pack_lo(s[2*fp+1][2], s[2*fp+1][3], ah[3]);

            const uint32_t vrow = (uint32_t)(fp * 16) + vLaneRow;
            #pragma unroll
            for (int g = 0; g < 4; g++) {
                const uint32_t vaddr = cur + 2 * QTILE + vrow * AROW
                                     + ((uint32_t)g * 16 + vLaneCol) * 2;
                uint32_t vh4[4], vl4[4];
                LDMAT4T(vh4, vaddr);
                LDMAT4T(vl4, vaddr + QTILE);
                mma16816(o[2 * g + 0], ah,  &vh4[0]);
                mma16816(o[2 * g + 1], ah,  &vh4[2]);
                mma16816(o[2 * g + 0], ah,  &vl4[0]);
                mma16816(o[2 * g + 1], ah,  &vl4[2]);
                mma16816(o[2 * g + 0], alr, &vh4[0]);
                mma16816(o[2 * g + 1], alr, &vh4[2]);
            }
        }
        __syncthreads();   // all warps done with this buffer before next prefetch overwrites
    }

    // ---- epilogue: normalize, write fp32 ----
    const float inv0 = 1.0f / l0;
    const float inv1 = 1.0f / l1;
    const int row0 = qBase + wid * 16 + (lane >> 2);
    #pragma unroll
    for (int nb = 0; nb < 8; nb++) {
        const int col = nb * 8 + (lane & 3) * 2;
        *(float2*)&O[gOff + (size_t)row0 * D_MODEL + col] =
            make_float2(o[nb][0] * inv0, o[nb][1] * inv0);
        *(float2*)&O[gOff + (size_t)(row0 + 8) * D_MODEL + col] =
            make_float2(o[nb][2] * inv1, o[nb][3] * inv1);
    }
}

// -------------------- launcher --------------------
extern "C" void kernel_launch(void* const* d_in, const int* in_sizes, int n_in,
                              void* d_out, int out_size)
{
    const float* q   = (const float*)d_in[0];
    const float* k   = (const float*)d_in[1];
    const float* v   = (const float*)d_in[2];
    const float* w_q = (const float*)d_in[3];
    const float* b_q = (const float*)d_in[4];
    const float* w_k = (const float*)d_in[5];
    const float* b_k = (const float*)d_in[6];
    const float* w_v = (const float*)d_in[7];
    const float* b_v = (const float*)d_in[8];
    const float* w_o = (const float*)d_in[9];
    const float* b_o = (const float*)d_in[10];
    float* out = (float*)d_out;

    __nv_bfloat16 *Qh, *Ql, *Kh, *Kl, *Vh, *Vl;
    float* AOp;
    cudaGetSymbolAddress((void**)&Qh, g_Qh);
    cudaGetSymbolAddress((void**)&Ql, g_Ql);
    cudaGetSymbolAddress((void**)&Kh, g_Kh);
    cudaGetSymbolAddress((void**)&Kl, g_Kl);
    cudaGetSymbolAddress((void**)&Vh, g_Vh);
    cudaGetSymbolAddress((void**)&Vl, g_Vl);
    cudaGetSymbolAddress((void**)&AOp, g_AO);

    cudaFuncSetAttribute(gemm_mma<true>,  cudaFuncAttributeMaxDynamicSharedMemorySize, GEMM_SMEM);
    cudaFuncSetAttribute(gemm_mma<false>, cudaFuncAttributeMaxDynamicSharedMemorySize, GEMM_SMEM);
    cudaFuncSetAttribute(attn_tc, cudaFuncAttributeMaxDynamicSharedMemorySize, ATTN_SMEM);

    dim3 gG(D_MODEL / 128, M_ROWS / 128);   // (8, 32)
    gemm_mma<true><<<gG, 256, GEMM_SMEM>>>(q, w_q, b_q, nullptr, Qh, Ql);
    gemm_mma<true><<<gG, 256, GEMM_SMEM>>>(k, w_k, b_k, nullptr, Kh, Kl);
    gemm_mma<true><<<gG, 256, GEMM_SMEM>>>(v, w_v, b_v, nullptr, Vh, Vl);

    dim3 gA(S_LEN / 128, B_SZ * N_HEADS);   // (16, 32)
    attn_tc<<<gA, 256, ATTN_SMEM>>>(Qh, Ql, Kh, Kl, Vh, Vl, AOp);

    gemm_mma<false><<<gG, 256, GEMM_SMEM>>>(AOp, w_o, b_o, out, nullptr, nullptr);
}

// round 5
// speedup vs baseline: 4.0827x; 1.0031x over previous
#include <cuda_runtime.h>
#include <cuda_bf16.h>
#include <math.h>
#include <stdint.h>

#define D_MODEL 1024
#define N_HEADS 16
#define DK 64
#define B_SZ 2
#define S_LEN 2048
#define M_ROWS (B_SZ * S_LEN)   // 4096

// -------------------- scratch (allocation-free) --------------------
__device__ __nv_bfloat16 g_Qh[M_ROWS * D_MODEL];
__device__ __nv_bfloat16 g_Ql[M_ROWS * D_MODEL];
__device__ __nv_bfloat16 g_Kh[M_ROWS * D_MODEL];
__device__ __nv_bfloat16 g_Kl[M_ROWS * D_MODEL];
__device__ __nv_bfloat16 g_Vh[M_ROWS * D_MODEL];
__device__ __nv_bfloat16 g_Vl[M_ROWS * D_MODEL];
__device__ float g_AO[M_ROWS * D_MODEL];

// ==================== helpers ====================
__device__ __forceinline__ uint32_t smem_to_u32(const void* p) {
    uint32_t a;
    asm("{ .reg .u64 t; cvta.to.shared.u64 t, %1; cvt.u32.u64 %0, t; }" : "=r"(a) : "l"(p));
    return a;
}

#define LDMAT4(r, addr) \
    asm volatile("ldmatrix.sync.aligned.m8n8.x4.shared.b16 {%0,%1,%2,%3}, [%4];" \
        : "=r"((r)[0]), "=r"((r)[1]), "=r"((r)[2]), "=r"((r)[3]) : "r"(addr))

#define LDMAT4T(r, addr) \
    asm volatile("ldmatrix.sync.aligned.m8n8.x4.trans.shared.b16 {%0,%1,%2,%3}, [%4];" \
        : "=r"((r)[0]), "=r"((r)[1]), "=r"((r)[2]), "=r"((r)[3]) : "r"(addr))

__device__ __forceinline__ void mma16816(float* d, const uint32_t* a, const uint32_t* b) {
    asm volatile(
        "mma.sync.aligned.m16n8k16.row.col.f32.bf16.bf16.f32 "
        "{%0,%1,%2,%3},{%4,%5,%6,%7},{%8,%9},{%0,%1,%2,%3};"
        : "+f"(d[0]), "+f"(d[1]), "+f"(d[2]), "+f"(d[3])
        : "r"(a[0]), "r"(a[1]), "r"(a[2]), "r"(a[3]), "r"(b[0]), "r"(b[1]));
}

__device__ __forceinline__ void cp16(uint32_t dst, const void* src) {
    asm volatile("cp.async.ca.shared.global [%0], [%1], 16;" :: "r"(dst), "l"(src) : "memory");
}
#define CP_COMMIT() asm volatile("cp.async.commit_group;" ::: "memory")
#define CP_WAIT(n)  asm volatile("cp.async.wait_group %0;" :: "n"(n) : "memory")

__device__ __forceinline__ uint32_t pack_hi(float a, float b) {
    __nv_bfloat162 t = __float22bfloat162_rn(make_float2(a, b));
    return *(uint32_t*)&t;
}
__device__ __forceinline__ uint32_t pack_lo(float a, float b, uint32_t hi) {
    __nv_bfloat162 h = *(__nv_bfloat162*)&hi;
    float2 f = __bfloat1622float2(h);
    __nv_bfloat162 t = __float22bfloat162_rn(make_float2(a - f.x, b - f.y));
    return *(uint32_t*)&t;
}

__device__ __forceinline__ void bf16x3_split(float4 v, uint2& hv, uint2& lv) {
    __nv_bfloat162 h01 = __float22bfloat162_rn(make_float2(v.x, v.y));
    __nv_bfloat162 h23 = __float22bfloat162_rn(make_float2(v.z, v.w));
    float2 f01 = __bfloat1622float2(h01);
    float2 f23 = __bfloat1622float2(h23);
    __nv_bfloat162 l01 = __float22bfloat162_rn(make_float2(v.x - f01.x, v.y - f01.y));
    __nv_bfloat162 l23 = __float22bfloat162_rn(make_float2(v.z - f23.x, v.w - f23.y));
    hv.x = *(uint32_t*)&h01; hv.y = *(uint32_t*)&h23;
    lv.x = *(uint32_t*)&l01; lv.y = *(uint32_t*)&l23;
}

// ==================== mma.sync bf16x3 GEMM core ====================
#define BK 32
#define ROW_B 80
#define TILE_SB (128 * ROW_B)
#define BUF_SB (4 * TILE_SB)
#define GEMM_SMEM (2 * BUF_SB)        // 81920 B

template <bool BF16OUT>
__device__ __forceinline__ void gemm_body(
    const float* __restrict__ X, const float* __restrict__ W,
    const float* __restrict__ bias, float* __restrict__ Y,
    __nv_bfloat16* __restrict__ Yh, __nv_bfloat16* __restrict__ Yl,
    char* sm, int mBase, int nBase)
{
    const uint32_t sbase = smem_to_u32(sm);
    const int tid   = threadIdx.x;
    const int lane  = tid & 31;
    const int wid   = tid >> 5;
    const int warpM = wid & 3;
    const int warpN = wid >> 2;

    const uint32_t aOff = (uint32_t)(warpM * 32 + (lane & 15)) * ROW_B + (uint32_t)(lane >> 4) * 16;
    const uint32_t bOff = (uint32_t)(warpN * 64 + (lane & 7) + ((lane >> 4) & 1) * 8) * ROW_B
                        + (uint32_t)((lane >> 3) & 1) * 16;

    const int gr  = tid >> 3;
    const int gc4 = (tid & 7) * 4;
    const uint32_t stsOff = (uint32_t)gr * ROW_B + (uint32_t)gc4 * 2;

    const float* Xg = X + (size_t)mBase * D_MODEL;
    const float* Wg = W + (size_t)nBase * D_MODEL;

    float acc[2][8][4] = {};

    float2 bv[8];
    #pragma unroll
    for (int ni = 0; ni < 8; ni++)
        bv[ni] = *(const float2*)&bias[nBase + warpN * 64 + ni * 8 + (lane & 3) * 2];

    {
        char* buf = sm;
        #pragma unroll
        for (int i = 0; i < 4; i++) {
            int r = gr + i * 32;
            uint32_t so = stsOff + (uint32_t)i * 32 * ROW_B;
            float4 xv = *(const float4*)(Xg + (size_t)r * D_MODEL + gc4);
            uint2 hv, lv; bf16x3_split(xv, hv, lv);
            *(uint2*)(buf + 0 * TILE_SB + so) = hv;
            *(uint2*)(buf + 1 * TILE_SB + so) = lv;
            float4 wv = *(const float4*)(Wg + (size_t)r * D_MODEL + gc4);
            bf16x3_split(wv, hv, lv);
            *(uint2*)(buf + 2 * TILE_SB + so) = hv;
            *(uint2*)(buf + 3 * TILE_SB + so) = lv;
        }
    }
    __syncthreads();

    const int NCH = D_MODEL / BK;
    for (int ch = 0; ch < NCH; ch++) {
        const int cur = ch & 1;

        float4 xr[4], wr[4];
        if (ch + 1 < NCH) {
            const int kt = (ch + 1) * BK;
            #pragma unroll
            for (int i = 0; i < 4; i++) {
                int r = gr + i * 32;
                xr[i] = *(const float4*)(Xg + (size_t)r * D_MODEL + kt + gc4);
                wr[i] = *(const float4*)(Wg + (size_t)r * D_MODEL + kt + gc4);
            }
        }

        const uint32_t aHi = sbase + (uint32_t)cur * BUF_SB + aOff;
        const uint32_t aLo = aHi + TILE_SB;
        const uint32_t bHi = sbase + (uint32_t)cur * BUF_SB + 2 * TILE_SB + bOff;
        const uint32_t bLo = bHi + TILE_SB;

        #pragma unroll
        for (int ks = 0; ks < 2; ks++) {
            uint32_t ah[2][4], al[2][4], bh[4][4], bl[4][4];
            LDMAT4(ah[0], aHi + ks * 32);
            LDMAT4(ah[1], aHi + 16 * ROW_B + ks * 32);
            LDMAT4(al[0], aLo + ks * 32);
            LDMAT4(al[1], aLo + 16 * ROW_B + ks * 32);
            #pragma unroll
            for (int p = 0; p < 4; p++) {
                LDMAT4(bh[p], bHi + (uint32_t)p * 16 * ROW_B + ks * 32);
                LDMAT4(bl[p], bLo + (uint32_t)p * 16 * ROW_B + ks * 32);
            }
            #pragma unroll
            for (int mi = 0; mi < 2; mi++) {
                #pragma unroll
                for (int p = 0; p < 4; p++) {
                    mma16816(acc[mi][2 * p + 0], ah[mi], &bh[p][0]);
                    mma16816(acc[mi][2 * p + 1], ah[mi], &bh[p][2]);
                    mma16816(acc[mi][2 * p + 0], ah[mi], &bl[p][0]);
                    mma16816(acc[mi][2 * p + 1], ah[mi], &bl[p][2]);
                    mma16816(acc[mi][2 * p + 0], al[mi], &bh[p][0]);
                    mma16816(acc[mi][2 * p + 1], al[mi], &bh[p][2]);
                }
            }
        }

        if (ch + 1 < NCH) {
            char* buf = sm + (cur ^ 1) * BUF_SB;
            #pragma unroll
            for (int i = 0; i < 4; i++) {
                uint32_t so = stsOff + (uint32_t)i * 32 * ROW_B;
                uint2 hv, lv;
                bf16x3_split(xr[i], hv, lv);
                *(uint2*)(buf + 0 * TILE_SB + so) = hv;
                *(uint2*)(buf + 1 * TILE_SB + so) = lv;
                bf16x3_split(wr[i], hv, lv);
                *(uint2*)(buf + 2 * TILE_SB + so) = hv;
                *(uint2*)(buf + 3 * TILE_SB + so) = lv;
            }
        }
        __syncthreads();
    }

    #pragma unroll
    for (int mi = 0; mi < 2; mi++) {
        const int row0 = mBase + warpM * 32 + mi * 16 + (lane >> 2);
        #pragma unroll
        for (int ni = 0; ni < 8; ni++) {
            const int col = nBase + warpN * 64 + ni * 8 + (lane & 3) * 2;
            float y00 = acc[mi][ni][0] + bv[ni].x;
            float y01 = acc[mi][ni][1] + bv[ni].y;
            float y10 = acc[mi][ni][2] + bv[ni].x;
            float y11 = acc[mi][ni][3] + bv[ni].y;
            if (BF16OUT) {
                uint32_t h0 = pack_hi(y00, y01);
                uint32_t l0 = pack_lo(y00, y01, h0);
                uint32_t h1 = pack_hi(y10, y11);
                uint32_t l1 = pack_lo(y10, y11, h1);
                *(uint32_t*)&Yh[(size_t)row0 * D_MODEL + col]       = h0;
                *(uint32_t*)&Yl[(size_t)row0 * D_MODEL + col]       = l0;
                *(uint32_t*)&Yh[(size_t)(row0 + 8) * D_MODEL + col] = h1;
                *(uint32_t*)&Yl[(size_t)(row0 + 8) * D_MODEL + col] = l1;
            } else {
                *(float2*)&Y[(size_t)row0 * D_MODEL + col]       = make_float2(y00, y01);
                *(float2*)&Y[(size_t)(row0 + 8) * D_MODEL + col] = make_float2(y10, y11);
            }
        }
    }
}

// fused QKV projection: grid.z selects (input, weight, bias, output pair)
__global__ void __launch_bounds__(256) gemm_qkv(
    const float* __restrict__ q, const float* __restrict__ k, const float* __restrict__ v,
    const float* __restrict__ wq, const float* __restrict__ wk, const float* __restrict__ wv,
    const float* __restrict__ bq, const float* __restrict__ bk, const float* __restrict__ bv_,
    __nv_bfloat16* __restrict__ Qh, __nv_bfloat16* __restrict__ Ql,
    __nv_bfloat16* __restrict__ Kh, __nv_bfloat16* __restrict__ Kl,
    __nv_bfloat16* __restrict__ Vh, __nv_bfloat16* __restrict__ Vl)
{
    extern __shared__ char sm[];
    const int z = blockIdx.z;
    const float* X = (z == 0) ? q : (z == 1) ? k : v;
    const float* W = (z == 0) ? wq : (z == 1) ? wk : wv;
    const float* B = (z == 0) ? bq : (z == 1) ? bk : bv_;
    __nv_bfloat16* Yh = (z == 0) ? Qh : (z == 1) ? Kh : Vh;
    __nv_bfloat16* Yl = (z == 0) ? Ql : (z == 1) ? Kl : Vl;
    gemm_body<true>(X, W, B, nullptr, Yh, Yl, sm, blockIdx.y * 128, blockIdx.x * 128);
}

// O projection (fp32 in, fp32 out)
__global__ void __launch_bounds__(256) gemm_out(
    const float* __restrict__ X, const float* __restrict__ W,
    const float* __restrict__ bias, float* __restrict__ Y)
{
    extern __shared__ char sm[];
    gemm_body<false>(X, W, bias, Y, nullptr, nullptr, sm, blockIdx.y * 128, blockIdx.x * 128);
}

// ==================== tensor-core flash attention (bf16x3) ====================
// CTA: 128 q-rows of one (b,h); 8 warps x 16 rows. KV tiles of 64 keys,
// double-buffered. smem = 110592 B -> 2 CTAs/SM.
#define AROW 144
#define QTILE (128 * AROW)            // 18432
#define KTILE (64 * AROW)             // 9216
#define KVBUF (4 * KTILE)             // 36864
#define ATTN_SMEM (2 * QTILE + 2 * KVBUF)   // 110592

__global__ void __launch_bounds__(256, 2) attn_tc(
    const __nv_bfloat16* __restrict__ Qh, const __nv_bfloat16* __restrict__ Ql,
    const __nv_bfloat16* __restrict__ Kh, const __nv_bfloat16* __restrict__ Kl,
    const __nv_bfloat16* __restrict__ Vh, const __nv_bfloat16* __restrict__ Vl,
    float* __restrict__ O)
{
    extern __shared__ char sm[];
    const uint32_t sbase = smem_to_u32(sm);

    const int tid  = threadIdx.x;
    const int lane = tid & 31;
    const int wid  = tid >> 5;
    const int bh = blockIdx.y;
    const int b = bh >> 4, h = bh & 15;
    const int qBase = blockIdx.x * 128;

    const size_t gOff = (size_t)b * S_LEN * D_MODEL + (size_t)h * DK;

    const uint32_t sQh = sbase;
    const uint32_t sQl = sbase + QTILE;
    const uint32_t sKV0 = sbase + 2 * QTILE;

    const int r = tid >> 3;
    const int c = tid & 7;

    // ---- issue Q (128 rows) + KV tile 0 (64 rows), one cp group ----
    {
        #pragma unroll
        for (int i = 0; i < 4; i++) {
            int rr = r + i * 32;
            uint32_t dofs = (uint32_t)rr * AROW + (uint32_t)c * 16;
            size_t so = gOff + (size_t)(qBase + rr) * D_MODEL + c * 8;
            cp16(sQh + dofs, Qh + so);
            cp16(sQl + dofs, Ql + so);
        }
        #pragma unroll
        for (int i = 0; i < 2; i++) {
            int rr = r + i * 32;
            uint32_t dofs = (uint32_t)rr * AROW + (uint32_t)c * 16;
            size_t sk = gOff + (size_t)rr * D_MODEL + c * 8;
            cp16(sKV0 + 0 * KTILE + dofs, Kh + sk);
            cp16(sKV0 + 1 * KTILE + dofs, Kl + sk);
            cp16(sKV0 + 2 * KTILE + dofs, Vh + sk);
            cp16(sKV0 + 3 * KTILE + dofs, Vl + sk);
        }
        CP_COMMIT();
    }

    float m0 = -1e30f, m1 = -1e30f, l0 = 0.0f, l1 = 0.0f;
    float o[8][4] = {};
    const float scale = 0.125f;

    const uint32_t aOffQ = (uint32_t)(wid * 16 + (lane & 15)) * AROW + (uint32_t)(lane >> 4) * 16;
    const uint32_t bOffK = (uint32_t)((lane & 7) + ((lane >> 4) & 1) * 8) * AROW
                         + (uint32_t)((lane >> 3) & 1) * 16;
    const uint32_t vLaneRow = (uint32_t)((lane & 7) + ((lane >> 3) & 1) * 8);
    const uint32_t vLaneCol = (uint32_t)(lane >> 4) * 8;

    const int NT = S_LEN / 64;   // 32
    for (int t = 0; t < NT; t++) {
        const uint32_t cur = sKV0 + (uint32_t)(t & 1) * KVBUF;

        if (t + 1 < NT) {
            const uint32_t nxt = sKV0 + (uint32_t)((t + 1) & 1) * KVBUF;
            #pragma unroll
            for (int i = 0; i < 2; i++) {
                int rr = r + i * 32;
                uint32_t dofs = (uint32_t)rr * AROW + (uint32_t)c * 16;
                size_t sk = gOff + (size_t)((t + 1) * 64 + rr) * D_MODEL + c * 8;
                cp16(nxt + 0 * KTILE + dofs, Kh + sk);
                cp16(nxt + 1 * KTILE + dofs, Kl + sk);
                cp16(nxt + 2 * KTILE + dofs, Vh + sk);
                cp16(nxt + 3 * KTILE + dofs, Vl + sk);
            }
            CP_COMMIT();
            CP_WAIT(1);
        } else {
            CP_WAIT(0);
        }
        __syncthreads();

        // Q fragments (reload per tile; keeps regs under the 2-CTA cap)
        uint32_t qh[4][4], ql[4][4];
        #pragma unroll
        for (int ks = 0; ks < 4; ks++) {
            LDMAT4(qh[ks], sQh + aOffQ + ks * 32);
            LDMAT4(ql[ks], sQl + aOffQ + ks * 32);
        }

        // ---- S = Q K^T  (64 keys -> 8 n8-frags) ----
        float s[8][4] = {};
        #pragma unroll
        for (int p = 0; p < 4; p++) {
            const uint32_t kb = cur + (uint32_t)p * 16 * AROW + bOffK;
            #pragma unroll
            for (int ks = 0; ks < 4; ks++) {
                uint32_t kh4[4], kl4[4];
                LDMAT4(kh4, kb + ks * 32);
                LDMAT4(kl4, kb + KTILE + ks * 32);
                mma16816(s[2 * p + 0], qh[ks], &kh4[0]);
                mma16816(s[2 * p + 1], qh[ks], &kh4[2]);
                mma16816(s[2 * p + 0], qh[ks], &kl4[0]);
                mma16816(s[2 * p + 1], qh[ks], &kl4[2]);
                mma16816(s[2 * p + 0], ql[ks], &kh4[0]);
                mma16816(s[2 * p + 1], ql[ks], &kh4[2]);
            }
        }

        // ---- online softmax ----
        float mx0 = -1e30f, mx1 = -1e30f;
        #pragma unroll
        for (int f = 0; f < 8; f++) {
            mx0 = fmaxf(mx0, fmaxf(s[f][0], s[f][1]));
            mx1 = fmaxf(mx1, fmaxf(s[f][2], s[f][3]));
        }
        mx0 = fmaxf(mx0, __shfl_xor_sync(0xffffffffu, mx0, 1));
        mx0 = fmaxf(mx0, __shfl_xor_sync(0xffffffffu, mx0, 2));
        mx1 = fmaxf(mx1, __shfl_xor_sync(0xffffffffu, mx1, 1));
        mx1 = fmaxf(mx1, __shfl_xor_sync(0xffffffffu, mx1, 2));

        float mn0 = fmaxf(m0, mx0 * scale);
        float mn1 = fmaxf(m1, mx1 * scale);
        float al0 = __expf(m0 - mn0);
        float al1 = __expf(m1 - mn1);
        m0 = mn0; m1 = mn1;

        float ls0 = 0.0f, ls1 = 0.0f;
        #pragma unroll
        for (int f = 0; f < 8; f++) {
            float p0 = __expf(fmaf(s[f][0], scale, -m0));
            float p1 = __expf(fmaf(s[f][1], scale, -m0));
            float p2 = __expf(fmaf(s[f][2], scale, -m1));
            float p3 = __expf(fmaf(s[f][3], scale, -m1));
            s[f][0] = p0; s[f][1] = p1; s[f][2] = p2; s[f][3] = p3;
            ls0 += p0 + p1;
            ls1 += p2 + p3;
        }
        ls0 += __shfl_xor_sync(0xffffffffu, ls0, 1);
        ls0 += __shfl_xor_sync(0xffffffffu, ls0, 2);
        ls1 += __shfl_xor_sync(0xffffffffu, ls1, 1);
        ls1 += __shfl_xor_sync(0xffffffffu, ls1, 2);
        l0 = l0 * al0 + ls0;
        l1 = l1 * al1 + ls1;

        #pragma unroll
        for (int nb = 0; nb < 8; nb++) {
            o[nb][0] *= al0; o[nb][1] *= al0;
            o[nb][2] *= al1; o[nb][3] *= al1;
        }

        // ---- O += P V ----
        #pragma unroll
        for (int fp = 0; fp < 4; fp++) {
            uint32_t ah[4], alr[4];
            ah[0]  = pack_hi(s[2*fp][0],   s[2*fp][1]);
            ah[1]  = pack_hi(s[2*fp][2],   s[2*fp][3]);
            ah[2]  = pack_hi(s[2*fp+1][0], s[2*fp+1][1]);
            ah[3]  = pack_hi(s[2*fp+1][2], s[2*fp+1][3]);
            alr[0] = pack_lo(s[2*fp][0],   s[2*fp][1],   ah[0]);
            alr[1] = pack_lo(s[2*fp][2],   s[2*fp][3],   ah[1]);
            alr[2] = pack_lo(s[2*fp+1][0], s[2*fp+1][1], ah[2]);
            alr[3] = pack_lo(s[2*fp+1][2], s[2*fp+1][3], ah[3]);

            const uint32_t vrow = (uint32_t)(fp * 16) + vLaneRow;
            #pragma unroll
            for (int g = 0; g < 4; g++) {
                const uint32_t vaddr = cur + 2 * KTILE + vrow * AROW
                                     + ((uint32_t)g * 16 + vLaneCol) * 2;
                uint32_t vh4[4], vl4[4];
                LDMAT4T(vh4, vaddr);
                LDMAT4T(vl4, vaddr + KTILE);
                mma16816(o[2 * g + 0], ah,  &vh4[0]);
                mma16816(o[2 * g + 1], ah,  &vh4[2]);
                mma16816(o[2 * g + 0], ah,  &vl4[0]);
                mma16816(o[2 * g + 1], ah,  &vl4[2]);
                mma16816(o[2 * g + 0], alr, &vh4[0]);
                mma16816(o[2 * g + 1], alr, &vh4[2]);
            }
        }
        __syncthreads();
    }

    const float inv0 = 1.0f / l0;
    const float inv1 = 1.0f / l1;
    const int row0 = qBase + wid * 16 + (lane >> 2);
    #pragma unroll
    for (int nb = 0; nb < 8; nb++) {
        const int col = nb * 8 + (lane & 3) * 2;
        *(float2*)&O[gOff + (size_t)row0 * D_MODEL + col] =
            make_float2(o[nb][0] * inv0, o[nb][1] * inv0);
        *(float2*)&O[gOff + (size_t)(row0 + 8) * D_MODEL + col] =
            make_float2(o[nb][2] * inv1, o[nb][3] * inv1);
    }
}

// -------------------- launcher --------------------
extern "C" void kernel_launch(void* const* d_in, const int* in_sizes, int n_in,
                              void* d_out, int out_size)
{
    const float* q   = (const float*)d_in[0];
    const float* k   = (const float*)d_in[1];
    const float* v   = (const float*)d_in[2];
    const float* w_q = (const float*)d_in[3];
    const float* b_q = (const float*)d_in[4];
    const float* w_k = (const float*)d_in[5];
    const float* b_k = (const float*)d_in[6];
    const float* w_v = (const float*)d_in[7];
    const float* b_v = (const float*)d_in[8];
    const float* w_o = (const float*)d_in[9];
    const float* b_o = (const float*)d_in[10];
    float* out = (float*)d_out;

    __nv_bfloat16 *Qh, *Ql, *Kh, *Kl, *Vh, *Vl;
    float* AOp;
    cudaGetSymbolAddress((void**)&Qh, g_Qh);
    cudaGetSymbolAddress((void**)&Ql, g_Ql);
    cudaGetSymbolAddress((void**)&Kh, g_Kh);
    cudaGetSymbolAddress((void**)&Kl, g_Kl);
    cudaGetSymbolAddress((void**)&Vh, g_Vh);
    cudaGetSymbolAddress((void**)&Vl, g_Vl);
    cudaGetSymbolAddress((void**)&AOp, g_AO);

    cudaFuncSetAttribute(gemm_qkv, cudaFuncAttributeMaxDynamicSharedMemorySize, GEMM_SMEM);
    cudaFuncSetAttribute(gemm_out, cudaFuncAttributeMaxDynamicSharedMemorySize, GEMM_SMEM);
    cudaFuncSetAttribute(attn_tc, cudaFuncAttributeMaxDynamicSharedMemorySize, ATTN_SMEM);

    dim3 gQKV(D_MODEL / 128, M_ROWS / 128, 3);   // (8, 32, 3)
    gemm_qkv<<<gQKV, 256, GEMM_SMEM>>>(q, k, v, w_q, w_k, w_v, b_q, b_k, b_v,
                                       Qh, Ql, Kh, Kl, Vh, Vl);

    dim3 gA(S_LEN / 128, B_SZ * N_HEADS);        // (16, 32)
    attn_tc<<<gA, 256, ATTN_SMEM>>>(Qh, Ql, Kh, Kl, Vh, Vl, AOp);

    dim3 gO(D_MODEL / 128, M_ROWS / 128);        // (8, 32)
    gemm_out<<<gO, 256, GEMM_SMEM>>>(AOp, w_o, b_o, out);
}